// round 15
// baseline (speedup 1.0000x reference)
#include <cuda_runtime.h>
#include <mma.h>
#include <cstdint>

using namespace nvcuda;

#define SCALE 0.17677669529663687f  // 1/sqrt(32)

__device__ float g_relbias[4 * 64 * 64];
__device__ float g_wts[65536];   // tf32-rounded [SCALE*Wq | Wk | Wv | Wo]
__device__ float g_qh[67108864]; // [524288][128] q-proj (scale folded), rounded
__device__ float g_k [67108864];
__device__ float g_v [67108864];
__device__ float g_x [67108864]; // attn output, tf32-rounded

__device__ __forceinline__ float rnd32(float x) {
    float r;
    asm("cvt.rna.tf32.f32 %0, %1;" : "=f"(r) : "f"(x));
    return r;
}

__global__ void relbias_kernel(const float* __restrict__ bias_table) {
    int idx = blockIdx.x * blockDim.x + threadIdx.x;
    if (idx < 4 * 64 * 64) {
        int h = idx >> 12;
        int n = (idx >> 6) & 63;
        int m = idx & 63;
        int r = ((n >> 3) - (m >> 3) + 7) * 15 + ((n & 7) - (m & 7) + 7);
        g_relbias[idx] = bias_table[r * 4 + h];
    }
}

// Wq gets SCALE folded in (so q-proj output is pre-scaled)
__global__ void roundwts_kernel(const float* __restrict__ Wq,
                                const float* __restrict__ Wkv,
                                const float* __restrict__ Wo) {
    int idx = blockIdx.x * blockDim.x + threadIdx.x;
    if (idx < 16384)       g_wts[idx] = rnd32(Wq[idx] * SCALE);
    else if (idx < 49152)  g_wts[idx] = rnd32(Wkv[idx - 16384]);
    else if (idx < 65536)  g_wts[idx] = rnd32(Wo[idx - 49152]);
}

// raw tf32 mma: D(m16n8) += A(m16k8) * B(k8n8)
__device__ __forceinline__ void mma168(float& c0, float& c1, float& c2, float& c3,
                                       uint32_t a0, uint32_t a1, uint32_t a2, uint32_t a3,
                                       uint32_t b0, uint32_t b1) {
    asm volatile(
        "mma.sync.aligned.m16n8k8.row.col.f32.tf32.tf32.f32 "
        "{%0,%1,%2,%3}, {%4,%5,%6,%7}, {%8,%9}, {%0,%1,%2,%3};"
        : "+f"(c0), "+f"(c1), "+f"(c2), "+f"(c3)
        : "r"(a0), "r"(a1), "r"(a2), "r"(a3), "r"(b0), "r"(b1));
}

// ldmatrix x4: loads the full m16k8 tf32 A fragment (a0..a3) in ONE instruction.
// Unit layout: m0=rows0-7/cols0-3, m1=rows8-15/cols0-3, m2=rows0-7/cols4-7, m3=rows8-15/cols4-7.
// Thread t receives element [t/4][t%4] of each unit == the mma fragment map.
__device__ __forceinline__ void ldsm_x4(uint32_t& a0, uint32_t& a1, uint32_t& a2, uint32_t& a3,
                                        uint32_t addr) {
    asm volatile("ldmatrix.sync.aligned.m8n8.x4.shared.b16 {%0,%1,%2,%3}, [%4];"
                 : "=r"(a0), "=r"(a1), "=r"(a2), "=r"(a3) : "r"(addr));
}

// ============= GEMM: C[256 rows,128] = A @ W^T  (512 thr, 16 warps x n8 strip) =============
// A fragments via ldmatrix.x4 (2 instr/kk instead of 8 LDS); B in registers.
__global__ void __launch_bounds__(512, 2)
mm3_kernel(const float* __restrict__ q, const float* __restrict__ kv,
           const float* __restrict__ bq, const float* __restrict__ bkv,
           const float* __restrict__ bo, float* __restrict__ out, int mode) {
    __shared__ float sA[2][32 * 132];

    const int tid = threadIdx.x;
    const int w = tid >> 5;
    const int lane = tid & 31;
    const int g = lane >> 2;
    const int tig = lane & 3;
    const int n0 = w * 8;
    const int cc = n0 + 2 * tig;

    const float* src; const float* Wg; const float* bias; float* dst;
    float scl; bool rin, rout; size_t row0;
    if (mode == 0) {
        int m = blockIdx.x % 3;          // interleave q/k/v -> kv L2 reuse
        size_t chunk = blockIdx.x / 3;
        row0 = chunk * 256;
        if (m == 0)      { src = q;  Wg = g_wts;         bias = bq;        dst = g_qh; scl = SCALE; }
        else if (m == 1) { src = kv; Wg = g_wts + 16384; bias = bkv;       dst = g_k;  scl = 1.0f; }
        else             { src = kv; Wg = g_wts + 32768; bias = bkv + 128; dst = g_v;  scl = 1.0f; }
        rin = true; rout = true;
    } else {
        row0 = (size_t)blockIdx.x * 256;
        src = g_x; Wg = g_wts + 49152; bias = bo; dst = out; scl = 1.0f;
        rin = false; rout = false;
    }

    const float bias0 = bias[cc] * scl;
    const float bias1 = bias[cc + 1] * scl;

    uint32_t B[16][2];
#pragma unroll
    for (int kk = 0; kk < 16; kk++) {
        B[kk][0] = __float_as_uint(Wg[(n0 + g) * 128 + kk * 8 + tig]);
        B[kk][1] = __float_as_uint(Wg[(n0 + g) * 128 + kk * 8 + tig + 4]);
    }

    // per-thread ldmatrix row address (bytes): row = lane&15, col-half = lane>>4
    const uint32_t abase = (uint32_t)__cvta_generic_to_shared(sA)
                         + (uint32_t)((lane & 15) * 132 + (lane >> 4) * 4) * 4u;

    {
        const float4* s4 = (const float4*)(src + row0 * 128);
#pragma unroll
        for (int u = 0; u < 2; u++) {
            int i = tid + 512 * u;
            float4 v = s4[i];
            if (rin) { v.x = rnd32(v.x); v.y = rnd32(v.y); v.z = rnd32(v.z); v.w = rnd32(v.w); }
            *(float4*)(sA[0] + (i >> 5) * 132 + (i & 31) * 4) = v;
        }
    }
    __syncthreads();

    for (int j = 0; j < 8; j++) {
        float4 pf0, pf1;
        if (j < 7) {
            const float4* n4 = (const float4*)(src + (row0 + (size_t)(j + 1) * 32) * 128);
            pf0 = n4[tid];
            pf1 = n4[tid + 512];
        }

        const uint32_t bufa = abase + (uint32_t)(j & 1) * 16896u;  // 32*132*4 bytes
        float c00 = bias0, c01 = bias1, c02 = bias0, c03 = bias1;
        float c10 = bias0, c11 = bias1, c12 = bias0, c13 = bias1;
#pragma unroll
        for (int kk = 0; kk < 16; kk++) {
            uint32_t a0, a1, a2, a3;
            ldsm_x4(a0, a1, a2, a3, bufa + kk * 32u);
            mma168(c00, c01, c02, c03, a0, a1, a2, a3, B[kk][0], B[kk][1]);
            uint32_t a4, a5, a6, a7;
            ldsm_x4(a4, a5, a6, a7, bufa + 8448u + kk * 32u);     // +16 rows (16*528B)
            mma168(c10, c11, c12, c13, a4, a5, a6, a7, B[kk][0], B[kk][1]);
        }

        if (rout) {
            c00 = rnd32(c00); c01 = rnd32(c01); c02 = rnd32(c02); c03 = rnd32(c03);
            c10 = rnd32(c10); c11 = rnd32(c11); c12 = rnd32(c12); c13 = rnd32(c13);
        }
        const size_t rb = row0 + (size_t)j * 32;
        *(float2*)(dst + (rb + g) * 128 + cc)      = make_float2(c00, c01);
        *(float2*)(dst + (rb + g + 8) * 128 + cc)  = make_float2(c02, c03);
        *(float2*)(dst + (rb + 16 + g) * 128 + cc) = make_float2(c10, c11);
        *(float2*)(dst + (rb + 24 + g) * 128 + cc) = make_float2(c12, c13);

        if (j < 7) {
            float* nb = sA[(j + 1) & 1];
#pragma unroll
            for (int u = 0; u < 2; u++) {
                int i = tid + 512 * u;
                float4 v = (u == 0) ? pf0 : pf1;
                if (rin) { v.x = rnd32(v.x); v.y = rnd32(v.y); v.z = rnd32(v.z); v.w = rnd32(v.w); }
                *(float4*)(nb + (i >> 5) * 132 + (i & 31) * 4) = v;
            }
        }
        __syncthreads();
    }
}

// ===================== attention core: overlapped smem (27KB), 8 CTAs/SM =====================
using FragA  = wmma::fragment<wmma::matrix_a, 16, 16, 8, wmma::precision::tf32, wmma::row_major>;
using FragB  = wmma::fragment<wmma::matrix_b, 16, 16, 8, wmma::precision::tf32, wmma::col_major>;
using FragBR = wmma::fragment<wmma::matrix_b, 16, 16, 8, wmma::precision::tf32, wmma::row_major>;
using FragC  = wmma::fragment<wmma::accumulator, 16, 16, 8, float>;

__global__ void __launch_bounds__(128, 8)
attn_kernel(const float* __restrict__ mask) {
    __shared__ float smA[4608];
    __shared__ float sV[2304];
    float* sQ = smA;
    float* sK = smA + 2304;
    float* Ph = smA;

    const int b = blockIdx.x >> 2;
    const int h = blockIdx.x & 3;
    const int tid = threadIdx.x;
    const int w = tid >> 5;
    const int lane = tid & 31;

    const float* qs = g_qh + (size_t)b * 8192 + h * 32;
    const float* ks = g_k + (size_t)b * 8192 + h * 32;
    const float* vs = g_v + (size_t)b * 8192 + h * 32;
    for (int i = tid; i < 512; i += 128) {
        int r = i >> 3, c4 = i & 7;
        *(float4*)(sQ + r * 36 + c4 * 4) = *(const float4*)(qs + r * 128 + c4 * 4);
        *(float4*)(sK + r * 36 + c4 * 4) = *(const float4*)(ks + r * 128 + c4 * 4);
        *(float4*)(sV + r * 36 + c4 * 4) = *(const float4*)(vs + r * 128 + c4 * 4);
    }
    __syncthreads();

    // S = qh @ k^T (K=32): warp w -> row-tile w, 4 col-tiles; acc in regs across barrier
    FragC acc[4];
#pragma unroll
    for (int t = 0; t < 4; t++) wmma::fill_fragment(acc[t], 0.0f);
#pragma unroll
    for (int k = 0; k < 32; k += 8) {
        FragA a;
        wmma::load_matrix_sync(a, sQ + w * 16 * 36 + k, 36);
#pragma unroll
        for (int t = 0; t < 4; t++) {
            FragB bf;
            wmma::load_matrix_sync(bf, sK + k + t * 16 * 36, 36);
            wmma::mma_sync(acc[t], a, bf, acc[t]);
        }
    }
    __syncthreads();   // all warps done READING sQ/sK -> overlay Ph

#pragma unroll
    for (int t = 0; t < 4; t++)
        wmma::store_matrix_sync(Ph + w * 16 * 68 + t * 16, acc[t], 68, wmma::mem_row_major);
    __syncwarp();      // warp-local: this warp softmaxes the rows it just wrote

    // softmax, NO max-shift (logits bounded ~|l|<8; exp safe in fp32; validated R12/R13).
    {
        const float* rb = g_relbias + h * 4096;
        const float* mk = mask + (size_t)(b & 4095) * 4096;
#pragma unroll
        for (int rr = 0; rr < 16; rr++) {
            int n = w * 16 + rr;
            float e0 = __expf(Ph[n * 68 + lane] + rb[n * 64 + lane] + mk[n * 64 + lane]);
            float e1 = __expf(Ph[n * 68 + lane + 32] + rb[n * 64 + lane + 32] + mk[n * 64 + lane + 32]);
            float s = e0 + e1;
#pragma unroll
            for (int o = 16; o; o >>= 1) s += __shfl_xor_sync(0xffffffffu, s, o);
            float inv = 1.0f / s;
            Ph[n * 68 + lane] = rnd32(e0 * inv);
            Ph[n * 68 + lane + 32] = rnd32(e1 * inv);
        }
    }
    __syncwarp();      // warp-local: PV reads the same rows this warp just wrote

    // x = P @ v (K=64, B row-major), rounded; store DIRECTLY to g_x
    FragC xc[2];
#pragma unroll
    for (int t = 0; t < 2; t++) wmma::fill_fragment(xc[t], 0.0f);
#pragma unroll
    for (int k = 0; k < 64; k += 8) {
        FragA a;
        wmma::load_matrix_sync(a, Ph + w * 16 * 68 + k, 68);
#pragma unroll
        for (int t = 0; t < 2; t++) {
            FragBR bf;
            wmma::load_matrix_sync(bf, sV + k * 36 + t * 16, 36);
            wmma::mma_sync(xc[t], a, bf, xc[t]);
        }
    }

    float* xd = g_x + (size_t)b * 8192 + h * 32 + (size_t)w * 16 * 128;
#pragma unroll
    for (int t = 0; t < 2; t++) {
#pragma unroll
        for (int i = 0; i < xc[t].num_elements; i++) xc[t].x[i] = rnd32(xc[t].x[i]);
        wmma::store_matrix_sync(xd + t * 16, xc[t], 128, wmma::mem_row_major);
    }
}

extern "C" void kernel_launch(void* const* d_in, const int* in_sizes, int n_in,
                              void* d_out, int out_size) {
    const float* q          = (const float*)d_in[0];
    const float* kv         = (const float*)d_in[1];
    const float* mask       = (const float*)d_in[2];
    const float* Wq         = (const float*)d_in[3];
    const float* bq         = (const float*)d_in[4];
    const float* Wkv        = (const float*)d_in[5];
    const float* bkv        = (const float*)d_in[6];
    const float* Wo         = (const float*)d_in[7];
    const float* bo         = (const float*)d_in[8];
    const float* bias_table = (const float*)d_in[9];
    float* out = (float*)d_out;

    relbias_kernel<<<64, 256>>>(bias_table);
    roundwts_kernel<<<256, 256>>>(Wq, Wkv, Wo);

    mm3_kernel<<<6144, 512>>>(q, kv, bq, bkv, bo, out, 0);   // qh, k, v projections
    attn_kernel<<<32768, 128>>>(mask);
    mm3_kernel<<<2048, 512>>>(q, kv, bq, bkv, bo, out, 1);   // out-proj
}

// round 16
// speedup vs baseline: 1.0885x; 1.0885x over previous
#include <cuda_runtime.h>
#include <mma.h>
#include <cstdint>

using namespace nvcuda;

#define SCALE 0.17677669529663687f  // 1/sqrt(32)

__device__ float g_relbias[4 * 64 * 64];
__device__ float g_wts[65536];   // tf32-rounded [SCALE*Wq | Wk | Wv | Wo]
__device__ float g_qh[67108864]; // [524288][128] q-proj (scale folded), rounded
__device__ float g_k [67108864];
__device__ float g_v [67108864];
__device__ float g_x [67108864]; // attn output, tf32-rounded

__device__ __forceinline__ float rnd32(float x) {
    float r;
    asm("cvt.rna.tf32.f32 %0, %1;" : "=f"(r) : "f"(x));
    return r;
}

__global__ void relbias_kernel(const float* __restrict__ bias_table) {
    int idx = blockIdx.x * blockDim.x + threadIdx.x;
    if (idx < 4 * 64 * 64) {
        int h = idx >> 12;
        int n = (idx >> 6) & 63;
        int m = idx & 63;
        int r = ((n >> 3) - (m >> 3) + 7) * 15 + ((n & 7) - (m & 7) + 7);
        g_relbias[idx] = bias_table[r * 4 + h];
    }
}

// Wq gets SCALE folded in (so q-proj output is pre-scaled)
__global__ void roundwts_kernel(const float* __restrict__ Wq,
                                const float* __restrict__ Wkv,
                                const float* __restrict__ Wo) {
    int idx = blockIdx.x * blockDim.x + threadIdx.x;
    if (idx < 16384)       g_wts[idx] = rnd32(Wq[idx] * SCALE);
    else if (idx < 49152)  g_wts[idx] = rnd32(Wkv[idx - 16384]);
    else if (idx < 65536)  g_wts[idx] = rnd32(Wo[idx - 49152]);
}

// raw tf32 mma: D(m16n8) += A(m16k8) * B(k8n8)
__device__ __forceinline__ void mma168(float& c0, float& c1, float& c2, float& c3,
                                       uint32_t a0, uint32_t a1, uint32_t a2, uint32_t a3,
                                       uint32_t b0, uint32_t b1) {
    asm volatile(
        "mma.sync.aligned.m16n8k8.row.col.f32.tf32.tf32.f32 "
        "{%0,%1,%2,%3}, {%4,%5,%6,%7}, {%8,%9}, {%0,%1,%2,%3};"
        : "+f"(c0), "+f"(c1), "+f"(c2), "+f"(c3)
        : "r"(a0), "r"(a1), "r"(a2), "r"(a3), "r"(b0), "r"(b1));
}

// ldmatrix x4: full m16k8 tf32 A fragment in one instruction (map verified R15).
__device__ __forceinline__ void ldsm_x4(uint32_t& a0, uint32_t& a1, uint32_t& a2, uint32_t& a3,
                                        uint32_t addr) {
    asm volatile("ldmatrix.sync.aligned.m8n8.x4.shared.b16 {%0,%1,%2,%3}, [%4];"
                 : "=r"(a0), "=r"(a1), "=r"(a2), "=r"(a3) : "r"(addr));
}

// ============= GEMM: C[256 rows,128] = A @ W^T  (512 thr, 16 warps x n8 strip) =============
__global__ void __launch_bounds__(512, 2)
mm3_kernel(const float* __restrict__ q, const float* __restrict__ kv,
           const float* __restrict__ bq, const float* __restrict__ bkv,
           const float* __restrict__ bo, float* __restrict__ out, int mode) {
    __shared__ float sA[2][32 * 132];

    const int tid = threadIdx.x;
    const int w = tid >> 5;
    const int lane = tid & 31;
    const int g = lane >> 2;
    const int tig = lane & 3;
    const int n0 = w * 8;
    const int cc = n0 + 2 * tig;

    const float* src; const float* Wg; const float* bias; float* dst;
    float scl; bool rin, rout; size_t row0;
    if (mode == 0) {
        int m = blockIdx.x % 3;          // interleave q/k/v -> kv L2 reuse
        size_t chunk = blockIdx.x / 3;
        row0 = chunk * 256;
        if (m == 0)      { src = q;  Wg = g_wts;         bias = bq;        dst = g_qh; scl = SCALE; }
        else if (m == 1) { src = kv; Wg = g_wts + 16384; bias = bkv;       dst = g_k;  scl = 1.0f; }
        else             { src = kv; Wg = g_wts + 32768; bias = bkv + 128; dst = g_v;  scl = 1.0f; }
        rin = true; rout = true;
    } else {
        row0 = (size_t)blockIdx.x * 256;
        src = g_x; Wg = g_wts + 49152; bias = bo; dst = out; scl = 1.0f;
        rin = false; rout = false;
    }

    const float bias0 = bias[cc] * scl;
    const float bias1 = bias[cc + 1] * scl;

    uint32_t B[16][2];
#pragma unroll
    for (int kk = 0; kk < 16; kk++) {
        B[kk][0] = __float_as_uint(Wg[(n0 + g) * 128 + kk * 8 + tig]);
        B[kk][1] = __float_as_uint(Wg[(n0 + g) * 128 + kk * 8 + tig + 4]);
    }

    const uint32_t abase = (uint32_t)__cvta_generic_to_shared(sA)
                         + (uint32_t)((lane & 15) * 132 + (lane >> 4) * 4) * 4u;

    {
        const float4* s4 = (const float4*)(src + row0 * 128);
#pragma unroll
        for (int u = 0; u < 2; u++) {
            int i = tid + 512 * u;
            float4 v = s4[i];
            if (rin) { v.x = rnd32(v.x); v.y = rnd32(v.y); v.z = rnd32(v.z); v.w = rnd32(v.w); }
            *(float4*)(sA[0] + (i >> 5) * 132 + (i & 31) * 4) = v;
        }
    }
    __syncthreads();

    for (int j = 0; j < 8; j++) {
        float4 pf0, pf1;
        if (j < 7) {
            const float4* n4 = (const float4*)(src + (row0 + (size_t)(j + 1) * 32) * 128);
            pf0 = n4[tid];
            pf1 = n4[tid + 512];
        }

        const uint32_t bufa = abase + (uint32_t)(j & 1) * 16896u;
        float c00 = bias0, c01 = bias1, c02 = bias0, c03 = bias1;
        float c10 = bias0, c11 = bias1, c12 = bias0, c13 = bias1;
#pragma unroll
        for (int kk = 0; kk < 16; kk++) {
            uint32_t a0, a1, a2, a3;
            ldsm_x4(a0, a1, a2, a3, bufa + kk * 32u);
            mma168(c00, c01, c02, c03, a0, a1, a2, a3, B[kk][0], B[kk][1]);
            uint32_t a4, a5, a6, a7;
            ldsm_x4(a4, a5, a6, a7, bufa + 8448u + kk * 32u);
            mma168(c10, c11, c12, c13, a4, a5, a6, a7, B[kk][0], B[kk][1]);
        }

        if (rout) {
            c00 = rnd32(c00); c01 = rnd32(c01); c02 = rnd32(c02); c03 = rnd32(c03);
            c10 = rnd32(c10); c11 = rnd32(c11); c12 = rnd32(c12); c13 = rnd32(c13);
        }
        const size_t rb = row0 + (size_t)j * 32;
        *(float2*)(dst + (rb + g) * 128 + cc)      = make_float2(c00, c01);
        *(float2*)(dst + (rb + g + 8) * 128 + cc)  = make_float2(c02, c03);
        *(float2*)(dst + (rb + 16 + g) * 128 + cc) = make_float2(c10, c11);
        *(float2*)(dst + (rb + 24 + g) * 128 + cc) = make_float2(c12, c13);

        if (j < 7) {
            float* nb = sA[(j + 1) & 1];
#pragma unroll
            for (int u = 0; u < 2; u++) {
                int i = tid + 512 * u;
                float4 v = (u == 0) ? pf0 : pf1;
                if (rin) { v.x = rnd32(v.x); v.y = rnd32(v.y); v.z = rnd32(v.z); v.w = rnd32(v.w); }
                *(float4*)(nb + (i >> 5) * 132 + (i & 31) * 4) = v;
            }
        }
        __syncthreads();
    }
}

// ===================== attention core: register-resident S + softmax =====================
using FragA  = wmma::fragment<wmma::matrix_a, 16, 16, 8, wmma::precision::tf32, wmma::row_major>;
using FragBR = wmma::fragment<wmma::matrix_b, 16, 16, 8, wmma::precision::tf32, wmma::row_major>;
using FragC  = wmma::fragment<wmma::accumulator, 16, 16, 8, float>;

__global__ void __launch_bounds__(128, 8)
attn_kernel(const float* __restrict__ mask) {
    __shared__ float smA[4608];
    __shared__ float sV[2304];
    float* sQ = smA;
    float* sK = smA + 2304;
    float* Ph = smA;           // overlay after S-GEMM reads complete

    const int b = blockIdx.x >> 2;
    const int h = blockIdx.x & 3;
    const int tid = threadIdx.x;
    const int w = tid >> 5;
    const int lane = tid & 31;
    const int g = lane >> 2;
    const int tig = lane & 3;

    const float* qs = g_qh + (size_t)b * 8192 + h * 32;
    const float* ks = g_k + (size_t)b * 8192 + h * 32;
    const float* vs = g_v + (size_t)b * 8192 + h * 32;
    for (int i = tid; i < 512; i += 128) {
        int r = i >> 3, c4 = i & 7;
        *(float4*)(sQ + r * 36 + c4 * 4) = *(const float4*)(qs + r * 128 + c4 * 4);
        *(float4*)(sK + r * 36 + c4 * 4) = *(const float4*)(ks + r * 128 + c4 * 4);
        *(float4*)(sV + r * 36 + c4 * 4) = *(const float4*)(vs + r * 128 + c4 * 4);
    }
    __syncthreads();

    // ---- S = qh @ k^T (K=32), raw mma: warp w owns rows w*16..+15, 8 n8 col-tiles ----
    // sc[t][0..1] = S[w16+g][t*8+2tig .. +1], sc[t][2..3] = S[w16+g+8][...]
    float sc[8][4];
#pragma unroll
    for (int t = 0; t < 8; t++) { sc[t][0] = 0.f; sc[t][1] = 0.f; sc[t][2] = 0.f; sc[t][3] = 0.f; }

    const uint32_t qbase = (uint32_t)__cvta_generic_to_shared(sQ)
                         + (uint32_t)((lane & 15) * 36 + (lane >> 4) * 4) * 4u
                         + (uint32_t)w * 2304u;   // w*16 rows * 144B
#pragma unroll
    for (int kc = 0; kc < 4; kc++) {
        uint32_t a0, a1, a2, a3;
        ldsm_x4(a0, a1, a2, a3, qbase + kc * 32u);
        const float* kb = sK + kc * 8 + tig;
#pragma unroll
        for (int t = 0; t < 8; t++) {
            uint32_t b0 = __float_as_uint(kb[(t * 8 + g) * 36]);
            uint32_t b1 = __float_as_uint(kb[(t * 8 + g) * 36 + 4]);
            mma168(sc[t][0], sc[t][1], sc[t][2], sc[t][3], a0, a1, a2, a3, b0, b1);
        }
    }

    // ---- softmax in registers (no max-shift; validated R12-R15) ----
    {
        const int nlo = w * 16 + g;
        const float* rbp = g_relbias + h * 4096;
        const float* mkp = mask + (size_t)(b & 4095) * 4096;
        float slo = 0.f, shi = 0.f;
#pragma unroll
        for (int t = 0; t < 8; t++) {
            const int c = t * 8 + 2 * tig;
            float2 r0 = *(const float2*)(rbp + nlo * 64 + c);
            float2 m0 = *(const float2*)(mkp + nlo * 64 + c);
            float2 r1 = *(const float2*)(rbp + (nlo + 8) * 64 + c);
            float2 m1 = *(const float2*)(mkp + (nlo + 8) * 64 + c);
            sc[t][0] = __expf(sc[t][0] + r0.x + m0.x);
            sc[t][1] = __expf(sc[t][1] + r0.y + m0.y);
            sc[t][2] = __expf(sc[t][2] + r1.x + m1.x);
            sc[t][3] = __expf(sc[t][3] + r1.y + m1.y);
            slo += sc[t][0] + sc[t][1];
            shi += sc[t][2] + sc[t][3];
        }
        // quad reduction (lanes g*4..g*4+3 own row nlo / nlo+8)
        slo += __shfl_xor_sync(0xffffffffu, slo, 1);
        slo += __shfl_xor_sync(0xffffffffu, slo, 2);
        shi += __shfl_xor_sync(0xffffffffu, shi, 1);
        shi += __shfl_xor_sync(0xffffffffu, shi, 2);
        float ilo = 1.0f / slo, ihi = 1.0f / shi;
#pragma unroll
        for (int t = 0; t < 8; t++) {
            sc[t][0] = rnd32(sc[t][0] * ilo);
            sc[t][1] = rnd32(sc[t][1] * ilo);
            sc[t][2] = rnd32(sc[t][2] * ihi);
            sc[t][3] = rnd32(sc[t][3] * ihi);
        }
    }
    __syncthreads();   // ALL warps done reading sQ/sK -> safe to overlay Ph

    // store P fragments (float2 per row-half per tile)
    {
        float* plo = Ph + (w * 16 + g) * 68 + 2 * tig;
        float* phi = Ph + (w * 16 + g + 8) * 68 + 2 * tig;
#pragma unroll
        for (int t = 0; t < 8; t++) {
            *(float2*)(plo + t * 8) = make_float2(sc[t][0], sc[t][1]);
            *(float2*)(phi + t * 8) = make_float2(sc[t][2], sc[t][3]);
        }
    }
    __syncwarp();      // PV reads only this warp's rows

    // ---- x = P @ v (K=64, B row-major), rounded; store directly to g_x ----
    FragC xc[2];
#pragma unroll
    for (int t = 0; t < 2; t++) wmma::fill_fragment(xc[t], 0.0f);
#pragma unroll
    for (int k = 0; k < 64; k += 8) {
        FragA a;
        wmma::load_matrix_sync(a, Ph + w * 16 * 68 + k, 68);
#pragma unroll
        for (int t = 0; t < 2; t++) {
            FragBR bf;
            wmma::load_matrix_sync(bf, sV + k * 36 + t * 16, 36);
            wmma::mma_sync(xc[t], a, bf, xc[t]);
        }
    }

    float* xd = g_x + (size_t)b * 8192 + h * 32 + (size_t)w * 16 * 128;
#pragma unroll
    for (int t = 0; t < 2; t++) {
#pragma unroll
        for (int i = 0; i < xc[t].num_elements; i++) xc[t].x[i] = rnd32(xc[t].x[i]);
        wmma::store_matrix_sync(xd + t * 16, xc[t], 128, wmma::mem_row_major);
    }
}

extern "C" void kernel_launch(void* const* d_in, const int* in_sizes, int n_in,
                              void* d_out, int out_size) {
    const float* q          = (const float*)d_in[0];
    const float* kv         = (const float*)d_in[1];
    const float* mask       = (const float*)d_in[2];
    const float* Wq         = (const float*)d_in[3];
    const float* bq         = (const float*)d_in[4];
    const float* Wkv        = (const float*)d_in[5];
    const float* bkv        = (const float*)d_in[6];
    const float* Wo         = (const float*)d_in[7];
    const float* bo         = (const float*)d_in[8];
    const float* bias_table = (const float*)d_in[9];
    float* out = (float*)d_out;

    relbias_kernel<<<64, 256>>>(bias_table);
    roundwts_kernel<<<256, 256>>>(Wq, Wkv, Wo);

    mm3_kernel<<<6144, 512>>>(q, kv, bq, bkv, bo, out, 0);   // qh, k, v projections
    attn_kernel<<<32768, 128>>>(mask);
    mm3_kernel<<<2048, 512>>>(q, kv, bq, bkv, bo, out, 1);   // out-proj
}